// round 4
// baseline (speedup 1.0000x reference)
#include <cuda_runtime.h>
#include <math.h>

#define DEVHOST __host__ __device__
typedef unsigned long long u64;

// ------------------------- compile-time structure -------------------------
DEVHOST constexpr int kTL (int i){ const int a[23]={0,0,0,0, 1,1,1,1,1,1, 2,2,2,2,2,2,2, 3,3,3,3,3,3}; return a[i]; }
DEVHOST constexpr int kTL1(int i){ const int a[23]={0,1,2,3, 1,1,2,2,3,3, 1,2,2,2,3,3,3, 2,2,3,3,3,3}; return a[i]; }
DEVHOST constexpr int kTL2(int i){ const int a[23]={0,1,2,3, 0,1,1,2,2,3, 1,0,1,2,1,2,3, 1,2,0,1,2,3}; return a[i]; }

DEVHOST constexpr int imax2(int a,int b){ return a>b?a:b; }
DEVHOST constexpr int imin2(int a,int b){ return a<b?a:b; }
DEVHOST constexpr int ilo_c(int l1,int l2,int m){ return imax2(-l1, m-l2); }
DEVHOST constexpr int ihi_c(int l1,int l2,int m){ return imin2( l1, m+l2); }
DEVHOST constexpr int rown_c(int l1,int l2,int m){ return ihi_c(l1,l2,m)-ilo_c(l1,l2,m)+1; }

DEVHOST constexpr int  kInOff(int l){ const int  a[4]={0,16,64,144};                       return a[l]; }
DEVHOST constexpr int  kMLf  (int l){ const int  a[4]={1024,1536,1792,1536};               return a[l]; }
DEVHOST constexpr long kMidBase(int l){ const long a[4]={0L,2097152L,11534336L,29884416L}; return a[l]; }
DEVHOST constexpr int  kTrip0(int l){ const int  a[4]={0,4,10,17};                         return a[l]; }
DEVHOST constexpr int  kSOff (int l){ const int  a[4]={0,1024,2560,4352};                  return a[l]; }
DEVHOST constexpr int  kWBase(int l){ const int  a[4]={0,16384,40960,69632};               return a[l]; }

// ------------------- compile-time Clebsch-Gordan values -------------------
DEVHOST constexpr double dfact(int n){ double r=1.0; for(int i=2;i<=n;++i) r*=(double)i; return r; }
DEVHOST constexpr double csqrt(double x){
    double g = (x>1.0)?x:1.0;
    for(int i=0;i<64;++i) g = 0.5*(g + x/g);
    return g;
}
DEVHOST constexpr double cgcoef(int l1,int m1,int l2,int m2,int l,int m){
    double pre = csqrt((double)(2*l+1)*dfact(l1+l2-l)*dfact(l1-l2+l)*dfact(-l1+l2+l)/dfact(l1+l2+l+1));
    pre = pre * csqrt(dfact(l+m)*dfact(l-m)*dfact(l1-m1)*dfact(l1+m1)*dfact(l2-m2)*dfact(l2+m2));
    double s = 0.0;
    for(int k=0;k<=l1+l2-l;++k){
        int d0=k, d1=l1+l2-l-k, d2=l1-m1-k, d3=l2+m2-k, d4=l-l2+m1+k, d5=l-l1-m2+k;
        if(d0<0||d1<0||d2<0||d3<0||d4<0||d5<0) continue;
        double den = dfact(d0)*dfact(d1)*dfact(d2)*dfact(d3)*dfact(d4)*dfact(d5);
        s += ((k&1)? -1.0 : 1.0)/den;
    }
    return pre*s;
}

// ------------------------------ device scratch ----------------------------
static constexpr int  NCH       = 5888;
static constexpr int  NBLK1     = 256;
static constexpr long MID_TOTAL = 51904512L;

__device__ float  g_part[(long)NBLK1 * NCH];
__device__ float  g_scale[NCH];
__device__ float2 g_wsc[94208];
__device__ float2 g_mid[MID_TOTAL];

// -------------------------------- f32x2 ops -------------------------------
__device__ __forceinline__ u64 pk2(float lo, float hi){
    u64 r; asm("mov.b64 %0,{%1,%2};" : "=l"(r) : "f"(lo), "f"(hi)); return r;
}
__device__ __forceinline__ void upk2(float& lo, float& hi, u64 v){
    asm("mov.b64 {%0,%1},%2;" : "=f"(lo), "=f"(hi) : "l"(v));
}
__device__ __forceinline__ u64 fma2(u64 a, u64 b, u64 c){
    u64 d; asm("fma.rn.f32x2 %0,%1,%2,%3;" : "=l"(d) : "l"(a), "l"(b), "l"(c)); return d;
}
__device__ __forceinline__ u64 add2(u64 a, u64 b){
    u64 d; asm("add.rn.f32x2 %0,%1,%2;" : "=l"(d) : "l"(a), "l"(b)); return d;
}

// --------------------- k1: tensor product + |mid|^2 partials --------------
template<int TR,int P,int J,int N,int D1,int D2>
struct JL {
    static __device__ __forceinline__ void run(const float2 (&f1)[D1], const float2 (&f2)[D2],
                                               float& ar, float& ai){
        constexpr int L=kTL(TR), L1=kTL1(TR), L2=kTL2(TR);
        constexpr int M  = P - L;
        constexpr int M1 = ilo_c(L1,L2,M) + J;
        constexpr int M2 = M - M1;
        constexpr float v = (float)cgcoef(L1,M1,L2,M2,L,M);
        float2 a = f1[M1+L1];
        float2 b = f2[M2+L2];
        ar += v*(a.x*b.x - a.y*b.y);
        ai += v*(a.x*b.y + a.y*b.x);
        if constexpr (J+1 < N) JL<TR,P,J+1,N,D1,D2>::run(f1,f2,ar,ai);
    }
};

template<int TR,int P,int D1,int D2>
struct PL {
    static __device__ __forceinline__ void run(const float2 (&f1)[D1], const float2 (&f2)[D2],
                                               float2* op, float& nsq){
        constexpr int L = kTL(TR);
        constexpr int N = rown_c(kTL1(TR),kTL2(TR),P-L);
        float ar=0.f, ai=0.f;
        JL<TR,P,0,N,D1,D2>::run(f1,f2,ar,ai);
        op[P] = make_float2(ar,ai);
        nsq += ar*ar + ai*ai;
        if constexpr (P+1 < 2*L+1) PL<TR,P+1,D1,D2>::run(f1,f2,op,nsq);
    }
};

template<int TR>
__device__ __forceinline__ void do_trip(const float* sF, int t, int s, int tid, int b0){
    constexpr int  L  = kTL(TR), L1 = kTL1(TR), L2 = kTL2(TR);
    constexpr int  D1 = 2*L1+1, D2 = 2*L2+1;
    constexpr int  ML = kMLf(L);
    constexpr long MB = kMidBase(L);
    const int cl = (TR - kTrip0(L))*256 + tid;
    float nsq = 0.f;
    for (int bs=0; bs<8; ++bs){
        const float2* fb = reinterpret_cast<const float2*>(sF + bs*512);
        float2 f1[D1], f2[D2];
        #pragma unroll
        for (int i=0;i<D1;++i) f1[i] = fb[kInOff(L1) + t*D1 + i];
        #pragma unroll
        for (int i=0;i<D2;++i) f2[i] = fb[kInOff(L2) + s*D2 + i];
        float2* op = g_mid + MB + (long)((b0+bs)*ML + cl)*(2*L+1);
        PL<TR,0,D1,D2>::run(f1,f2,op,nsq);
    }
    g_part[(long)blockIdx.x*NCH + TR*256 + tid] = nsq;
}

template<int TR>
struct TripsAll {
    static __device__ __forceinline__ void run(const float* sF, int t, int s, int tid, int b0){
        do_trip<TR>(sF,t,s,tid,b0);
        if constexpr (TR+1 < 23) TripsAll<TR+1>::run(sF,t,s,tid,b0);
    }
};

__global__ void __launch_bounds__(256) k1_kernel(const float* __restrict__ act){
    __shared__ float sF[8*512];
    const int tid = threadIdx.x;
    const int b0  = blockIdx.x*8;
    const float4* src = reinterpret_cast<const float4*>(act + (long)b0*512);
    float4* dst = reinterpret_cast<float4*>(sF);
    for (int i=tid; i<1024; i+=256) dst[i] = src[i];
    __syncthreads();
    TripsAll<0>::run(sF, tid>>4, tid&15, tid, b0);
}

// ------------- k2a: reduce partials -> inverse (new_std + eps) ------------
__global__ void k2a_kernel(const float* __restrict__ bn){
    int c = blockIdx.x*256 + threadIdx.x;
    if (c >= NCH) return;
    int l = (c<1024)?0:((c<2560)?1:((c<4352)?2:3));
    float s = 0.f;
    for (int i=0;i<NBLK1;++i) s += g_part[(long)i*NCH + c];
    float bstd = sqrtf(s / (2048.0f * (float)(2*l+1)));
    g_scale[c] = 1.0f/(0.5f*(bn[c] + bstd) + 1e-5f);
}

// --------------------- k2b: fold scale into W ------------------------------
__global__ void k2b_kernel(const float* __restrict__ W){
    int r = blockIdx.x*256 + threadIdx.x;
    if (r >= 94208) return;
    int l = (r<16384)?0:((r<40960)?1:((r<69632)?2:3));
    int rr = r - kWBase(l);
    int c  = rr % kMLf(l);
    float sc = g_scale[kSOff(l) + c];
    g_wsc[r] = make_float2(W[2*r]*sc, W[2*r+1]*sc);
}

// -------- k3: out[b,o,p] = sum_c Wsc[o,c]*mid[b,c,p]  (complex, f32x2) -----
// 256 threads = 8 c-split x 8 o-groups(2o) x 4 b-groups(2b); block = 8 batches
template<int L>
__global__ void __launch_bounds__(256) k3_kernel(float* __restrict__ out){
    constexpr int  DP   = 2*L+1;
    constexpr int  ML   = kMLf(L);
    constexpr long MB   = kMidBase(L);
    constexpr int  WB   = kWBase(L);
    constexpr int  OROW = kInOff(L);

    const int tid = threadIdx.x;
    const int cs  = tid & 7;
    const int og  = (tid>>3) & 7;
    const int bg  = tid >> 6;
    const int o0  = og*2;
    const int b0  = blockIdx.x*8 + bg*2;

    u64 acc[2][2][DP];
    #pragma unroll
    for (int bi=0;bi<2;++bi)
        #pragma unroll
        for (int oi=0;oi<2;++oi)
            #pragma unroll
            for (int p=0;p<DP;++p) acc[bi][oi][p] = 0ULL;

    const float2* wp0 = g_wsc + WB + (long)o0*ML;
    const float2* wp1 = wp0 + ML;
    const float2* mb0 = g_mid + MB + (long)b0*ML*DP;
    const float2* mb1 = mb0 + (long)ML*DP;

    for (int c=cs; c<ML; c+=8){
        float2 w0 = __ldg(wp0 + c);
        float2 w1 = __ldg(wp1 + c);
        u64 wxx0 = pk2(w0.x, w0.x), wyy0 = pk2(-w0.y, w0.y);
        u64 wxx1 = pk2(w1.x, w1.x), wyy1 = pk2(-w1.y, w1.y);
        #pragma unroll
        for (int bi=0;bi<2;++bi){
            const float2* mp = (bi ? mb1 : mb0) + (long)c*DP;
            #pragma unroll
            for (int p=0;p<DP;++p){
                float2 m = __ldg(mp + p);
                u64 mxy = pk2(m.x, m.y);
                u64 myx = pk2(m.y, m.x);
                acc[bi][0][p] = fma2(wxx0, mxy, acc[bi][0][p]);
                acc[bi][0][p] = fma2(wyy0, myx, acc[bi][0][p]);
                acc[bi][1][p] = fma2(wxx1, mxy, acc[bi][1][p]);
                acc[bi][1][p] = fma2(wyy1, myx, acc[bi][1][p]);
            }
        }
    }

    // reduce over cs (lane bits 0..2) — deterministic butterfly
    #pragma unroll
    for (int bi=0;bi<2;++bi)
        #pragma unroll
        for (int oi=0;oi<2;++oi)
            #pragma unroll
            for (int p=0;p<DP;++p){
                u64 v = acc[bi][oi][p];
                v = add2(v, __shfl_xor_sync(0xffffffffu, v, 1));
                v = add2(v, __shfl_xor_sync(0xffffffffu, v, 2));
                v = add2(v, __shfl_xor_sync(0xffffffffu, v, 4));
                acc[bi][oi][p] = v;
            }

    if (cs == 0){
        #pragma unroll
        for (int bi=0;bi<2;++bi)
            #pragma unroll
            for (int oi=0;oi<2;++oi)
                #pragma unroll
                for (int p=0;p<DP;++p){
                    float x,y; upk2(x,y,acc[bi][oi][p]);
                    long row = (long)(b0+bi)*256 + OROW + (o0+oi)*DP + p;
                    reinterpret_cast<float2*>(out)[row] = make_float2(x,y);
                }
    }
}

// --------------------------------- launch ---------------------------------
extern "C" void kernel_launch(void* const* d_in, const int* in_sizes, int n_in,
                              void* d_out, int out_size){
    const float* act = nullptr;
    const float* W   = nullptr;
    const float* bn  = nullptr;
    for (int i=0;i<n_in;++i){
        if      (in_sizes[i] == 1048576) act = (const float*)d_in[i];
        else if (in_sizes[i] == 188416)  W   = (const float*)d_in[i];
        else if (in_sizes[i] == 5888)    bn  = (const float*)d_in[i];
    }
    float* out = (float*)d_out;

    k1_kernel<<<256,256>>>(act);
    k2a_kernel<<<23,256>>>(bn);
    k2b_kernel<<<368,256>>>(W);
    k3_kernel<0><<<256,256>>>(out);
    k3_kernel<1><<<256,256>>>(out);
    k3_kernel<2><<<256,256>>>(out);
    k3_kernel<3><<<256,256>>>(out);
}